// round 15
// baseline (speedup 1.0000x reference)
#include <cuda_runtime.h>
#include <cuda_fp16.h>
#include <cstdint>

// Problem constants: B=8, D=8, H=W=56, C=128, 4 heads x 32, windows (8,7,7),
// all pads zero. xy: 4096 windows x 49 tok; th/tw: 3584 x 56.
//
// 2 windows per CTA (1024 thr). ldmatrix on plain row-major smem (stride 136
// halves -> conflict-free LDSM). P register-resident. q+k in one pass.
// R15: ZERO full-CTA barriers. Weight buffers are group-partitioned: the 4
// warps sharing n0 (2 per half) form a group; one warp stages that group's
// 16 rows of W0/W1 via cp.async and a 128-thread named barrier (bar.sync
// 3+group) gates the reads. Activations use 512-thread half barriers.
// Stagers alternate halves by group parity. th/tw merged (REDG, commutative).

static constexpr int SH   = 136;  // stride (halves) X/Q/K rows
static constexpr int WSH  = 136;  // stride staged weight rows
static constexpr int VS   = 136;  // stride V rows

static constexpr int OFF_X  = 0;                    // 64 x SH (x, later attn out)
static constexpr int OFF_Q  = OFF_X + 64 * SH;
static constexpr int OFF_K  = OFF_Q + 64 * SH;
static constexpr int OFF_V  = OFF_K + 64 * SH;
static constexpr int ACT_HALVES = OFF_V + 64 * VS;  // 34816
static constexpr int OFF_W0 = 2 * ACT_HALVES;       // weight buffer 0
static constexpr int OFF_W1 = OFF_W0 + 128 * WSH;   // weight buffer 1
static constexpr int TOT_HALVES = OFF_W1 + 128 * WSH;          // 104448
static constexpr int SMEM_BYTES = TOT_HALVES * 2 + 128 * 4;    // 209408 (1 CTA/SM)

// Pre-converted fp16 weights, PLAIN transposed: [n][k].
__device__ __align__(16) __half g_qkvwt[3][384 * 128];
__device__ __align__(16) __half g_projwt[3][128 * 128];

template <int BRANCH>
__device__ __forceinline__ int tok_index(int win, int tt) {
    if (BRANCH == 0) {                 // xy: (b, d, hb, wb) x (hh, ww)
        int b  = win >> 9;
        int d  = (win >> 6) & 7;
        int hb = (win >> 3) & 7;
        int wb = win & 7;
        int hh = tt / 7, wq = tt - hh * 7;
        return ((b * 8 + d) * 56 + hb * 7 + hh) * 56 + wb * 7 + wq;
    } else if (BRANCH == 1) {          // th: (b, hb, w) x (dd, hh)
        int b  = win / 448;
        int r  = win - b * 448;
        int hb = r / 56;
        int w  = r - hb * 56;
        int dd = tt / 7, hh = tt - dd * 7;
        return ((b * 8 + dd) * 56 + hb * 7 + hh) * 56 + w;
    } else {                           // tw: (b, h, wb) x (dd, ww)
        int b  = win / 448;
        int r  = win - b * 448;
        int h  = r >> 3;
        int wb = r & 7;
        int dd = tt / 7, wq = tt - dd * 7;
        return ((b * 8 + dd) * 56 + h) * 56 + wb * 7 + wq;
    }
}

__device__ __forceinline__ void mma16(float4& d, uint32_t a0, uint32_t a1,
                                      uint32_t a2, uint32_t a3,
                                      uint32_t b0, uint32_t b1) {
    asm volatile(
        "mma.sync.aligned.m16n8k16.row.col.f32.f16.f16.f32 "
        "{%0,%1,%2,%3}, {%4,%5,%6,%7}, {%8,%9}, {%0,%1,%2,%3};\n"
        : "+f"(d.x), "+f"(d.y), "+f"(d.z), "+f"(d.w)
        : "r"(a0), "r"(a1), "r"(a2), "r"(a3), "r"(b0), "r"(b1));
}

__device__ __forceinline__ void ldsm_x4(uint32_t& r0, uint32_t& r1,
                                        uint32_t& r2, uint32_t& r3, uint32_t addr) {
    asm volatile("ldmatrix.sync.aligned.m8n8.x4.shared.b16 {%0,%1,%2,%3}, [%4];"
                 : "=r"(r0), "=r"(r1), "=r"(r2), "=r"(r3) : "r"(addr));
}
__device__ __forceinline__ void ldsm_x2(uint32_t& r0, uint32_t& r1, uint32_t addr) {
    asm volatile("ldmatrix.sync.aligned.m8n8.x2.shared.b16 {%0,%1}, [%2];"
                 : "=r"(r0), "=r"(r1) : "r"(addr));
}
__device__ __forceinline__ void ldsm_x4_t(uint32_t& r0, uint32_t& r1,
                                          uint32_t& r2, uint32_t& r3, uint32_t addr) {
    asm volatile("ldmatrix.sync.aligned.m8n8.x4.trans.shared.b16 {%0,%1,%2,%3}, [%4];"
                 : "=r"(r0), "=r"(r1), "=r"(r2), "=r"(r3) : "r"(addr));
}

__device__ __forceinline__ void cp16(uint32_t dst, const void* src) {
    asm volatile("cp.async.cg.shared.global [%0], [%1], 16;" :: "r"(dst), "l"(src));
}
__device__ __forceinline__ void cp_commit() {
    asm volatile("cp.async.commit_group;" ::: "memory");
}
template <int N>
__device__ __forceinline__ void cp_wait() {
    asm volatile("cp.async.wait_group %0;" :: "n"(N) : "memory");
}
__device__ __forceinline__ void bar_named(int id, int cnt) {
    asm volatile("bar.sync %0, %1;" :: "r"(id), "r"(cnt) : "memory");
}

__device__ __forceinline__ uint32_t h2u(float a, float b) {
    __half2 h = __floats2half2_rn(a, b);
    return *(uint32_t*)&h;
}

// ---------------- weight pre-conversion (plain transpose) ----------------
__global__ void conv_weights(const float* __restrict__ w0, const float* __restrict__ w1,
                             const float* __restrict__ w2, const float* __restrict__ p0,
                             const float* __restrict__ p1, const float* __restrict__ p2) {
    int tid = blockIdx.x * 256 + threadIdx.x;
    const int QK = 3 * 384 * 128;
    if (tid < QK) {
        int br  = tid / (384 * 128);
        int rem = tid - br * 384 * 128;
        int n = rem >> 7, k = rem & 127;
        const float* src = (br == 0) ? w0 : (br == 1 ? w1 : w2);
        g_qkvwt[br][rem] = __float2half_rn(src[k * 384 + n]);
    } else {
        int t2  = tid - QK;
        int br  = t2 / (128 * 128);
        int rem = t2 - br * 16384;
        int n = rem >> 7, k = rem & 127;
        const float* src = (br == 0) ? p0 : (br == 1 ? p1 : p2);
        g_projwt[br][rem] = __float2half_rn(src[k * 128 + n]);
    }
}

// ------------- fused window attention body, TWO windows per CTA -------------
template <int BRANCH, int NTOK>
__device__ __forceinline__ void
win_body(int cta, const float* __restrict__ x,
         const float* __restrict__ qkvb, const float* __restrict__ projb,
         float* __restrict__ out)
{
    extern __shared__ __align__(16) __half smh[];
    int* tokidx = (int*)(smh + TOT_HALVES);
    const uint32_t smem_u32 = (uint32_t)__cvta_generic_to_shared(smh);

    const int t    = threadIdx.x;          // 0..1023
    const int wh   = t >> 9;               // window half 0/1
    const int tl   = t & 511;
    const int lane = t & 31;
    const int wrp  = tl >> 5;              // local warp 0..15
    const int g    = lane >> 2;
    const int tg   = lane & 3;
    const int win  = cta * 2 + wh;
    const int base = wh * ACT_HALVES;

    const int aRow = lane & 15;
    const int aCol = (lane >> 4) << 3;
    const int bRow = (lane & 7) + ((lane >> 4) << 3);
    const int bCol = ((lane >> 3) & 1) << 3;

    // Weight group: 4 warps (2 per half) share rows [16*grp, 16*grp+16).
    const int grp       = wrp >> 1;                       // 0..7
    const bool stager   = ((grp & 1) == wh) && ((wrp & 1) == 0);
    const int  gbar     = 3 + grp;                        // barrier ids 3..10
    const int  row0     = grp * 16;

    // ---- stage q->W0, k->W1 (group rows only, one stager warp) ----
    if (stager) {
        const __half* wq = g_qkvwt[BRANCH];
        const __half* wk = g_qkvwt[BRANCH] + 128 * 128;
        #pragma unroll
        for (int i = 0; i < 8; i++) {
            int idx = lane + 32 * i;              // 256 chunks = 16 rows x 16
            int rr = row0 + (idx >> 4), c8 = idx & 15;
            cp16(smem_u32 + (uint32_t)(OFF_W0 + rr * WSH + c8 * 8) * 2,
                 wq + rr * 128 + c8 * 8);
            cp16(smem_u32 + (uint32_t)(OFF_W1 + rr * WSH + c8 * 8) * 2,
                 wk + rr * 128 + c8 * 8);
        }
        cp_commit();
    }

    if (tl < NTOK) tokidx[wh * 64 + tl] = tok_index<BRANCH>(win, tl);

    // ---- x -> X (fp16, plain rows), pad rows zeroed ----
    for (int idx = tl; idx < 64 * 32; idx += 512) {
        int r = idx >> 5, q = idx & 31;
        uint2 u = make_uint2(0u, 0u);
        if (r < NTOK) {
            float4 v = *(const float4*)
                (x + (size_t)tok_index<BRANCH>(win, r) * 128 + q * 4);
            u.x = h2u(v.x, v.y);
            u.y = h2u(v.z, v.w);
        }
        *(uint2*)&smh[base + OFF_X + r * SH + q * 4] = u;
    }
    bar_named(1 + wh, 512);      // HB-A: x visible within half

    const int mb = (wrp & 1) * 2;        // m-tiles {mb, mb+1}
    const int n0 = grp * 16;             // n columns [n0, n0+16)
    const float qscale = 0.1767766952966369f;

    const uint32_t xA0 = smem_u32 +
        (uint32_t)(base + OFF_X + (mb * 16 + aRow) * SH + aCol) * 2;
    const uint32_t xA1 = xA0 + 16u * SH * 2u;
    const uint32_t wB0 = smem_u32 + (uint32_t)(OFF_W0 + (n0 + bRow) * WSH + bCol) * 2;
    const uint32_t wB1 = smem_u32 + (uint32_t)(OFF_W1 + (n0 + bRow) * WSH + bCol) * 2;

    if (stager) cp_wait<0>();
    bar_named(gbar, 128);        // GB-1: group q/k rows ready

    // ---- q + k in ONE pass (A loaded once, B from W0/W1 group rows) ----
    {
        float4 accq[2][2], acck[2][2];
        #pragma unroll
        for (int n = 0; n < 2; n++) {
            float q0 = qkvb[n0 + n * 8 + 2 * tg];
            float q1 = qkvb[n0 + n * 8 + 2 * tg + 1];
            float k0 = qkvb[128 + n0 + n * 8 + 2 * tg];
            float k1 = qkvb[128 + n0 + n * 8 + 2 * tg + 1];
            accq[0][n] = make_float4(q0, q1, q0, q1);
            accq[1][n] = accq[0][n];
            acck[0][n] = make_float4(k0, k1, k0, k1);
            acck[1][n] = acck[0][n];
        }
        #pragma unroll 2
        for (int kt = 0; kt < 8; kt++) {
            uint32_t koff = kt * 32u;
            uint32_t A0[4], A1[4], Bq[4], Bk[4];
            ldsm_x4(A0[0], A0[1], A0[2], A0[3], xA0 + koff);
            ldsm_x4(A1[0], A1[1], A1[2], A1[3], xA1 + koff);
            ldsm_x4(Bq[0], Bq[1], Bq[2], Bq[3], wB0 + koff);
            ldsm_x4(Bk[0], Bk[1], Bk[2], Bk[3], wB1 + koff);
            mma16(accq[0][0], A0[0], A0[1], A0[2], A0[3], Bq[0], Bq[1]);
            mma16(accq[0][1], A0[0], A0[1], A0[2], A0[3], Bq[2], Bq[3]);
            mma16(accq[1][0], A1[0], A1[1], A1[2], A1[3], Bq[0], Bq[1]);
            mma16(accq[1][1], A1[0], A1[1], A1[2], A1[3], Bq[2], Bq[3]);
            mma16(acck[0][0], A0[0], A0[1], A0[2], A0[3], Bk[0], Bk[1]);
            mma16(acck[0][1], A0[0], A0[1], A0[2], A0[3], Bk[2], Bk[3]);
            mma16(acck[1][0], A1[0], A1[1], A1[2], A1[3], Bk[0], Bk[1]);
            mma16(acck[1][1], A1[0], A1[1], A1[2], A1[3], Bk[2], Bk[3]);
        }
        #pragma unroll
        for (int m = 0; m < 2; m++) {
            int r = (mb + m) * 16 + g;
            #pragma unroll
            for (int n = 0; n < 2; n++) {
                int c = n0 + n * 8 + 2 * tg;
                *(uint32_t*)&smh[base + OFF_Q + r * SH + c] =
                    h2u(accq[m][n].x * qscale, accq[m][n].y * qscale);
                *(uint32_t*)&smh[base + OFF_Q + (r + 8) * SH + c] =
                    h2u(accq[m][n].z * qscale, accq[m][n].w * qscale);
                *(uint32_t*)&smh[base + OFF_K + r * SH + c] =
                    h2u(acck[m][n].x, acck[m][n].y);
                *(uint32_t*)&smh[base + OFF_K + (r + 8) * SH + c] =
                    h2u(acck[m][n].z, acck[m][n].w);
            }
        }
    }
    bar_named(gbar, 128);        // GB-2: group done READING q/k rows

    // ---- restage v->W0, proj->W1 (group rows, same stager) ----
    if (stager) {
        const __half* wv = g_qkvwt[BRANCH] + 2 * 128 * 128;
        const __half* pw = g_projwt[BRANCH];
        #pragma unroll
        for (int i = 0; i < 8; i++) {
            int idx = lane + 32 * i;
            int rr = row0 + (idx >> 4), c8 = idx & 15;
            cp16(smem_u32 + (uint32_t)(OFF_W0 + rr * WSH + c8 * 8) * 2,
                 wv + rr * 128 + c8 * 8);
            cp16(smem_u32 + (uint32_t)(OFF_W1 + rr * WSH + c8 * 8) * 2,
                 pw + rr * 128 + c8 * 8);
        }
        cp_commit();
        cp_wait<0>();
    }
    bar_named(gbar, 128);        // GB-3: group v/proj rows ready

    // ---- v chunk (W0 group rows) ----
    {
        float4 acc[2][2];
        #pragma unroll
        for (int n = 0; n < 2; n++) {
            float b0 = qkvb[256 + n0 + n * 8 + 2 * tg];
            float b1 = qkvb[256 + n0 + n * 8 + 2 * tg + 1];
            acc[0][n] = make_float4(b0, b1, b0, b1);
            acc[1][n] = acc[0][n];
        }
        #pragma unroll 4
        for (int kt = 0; kt < 8; kt++) {
            uint32_t koff = kt * 32u;
            uint32_t A0[4], A1[4], Bv[4];
            ldsm_x4(A0[0], A0[1], A0[2], A0[3], xA0 + koff);
            ldsm_x4(A1[0], A1[1], A1[2], A1[3], xA1 + koff);
            ldsm_x4(Bv[0], Bv[1], Bv[2], Bv[3], wB0 + koff);
            mma16(acc[0][0], A0[0], A0[1], A0[2], A0[3], Bv[0], Bv[1]);
            mma16(acc[0][1], A0[0], A0[1], A0[2], A0[3], Bv[2], Bv[3]);
            mma16(acc[1][0], A1[0], A1[1], A1[2], A1[3], Bv[0], Bv[1]);
            mma16(acc[1][1], A1[0], A1[1], A1[2], A1[3], Bv[2], Bv[3]);
        }
        #pragma unroll
        for (int m = 0; m < 2; m++) {
            int r = (mb + m) * 16 + g;
            #pragma unroll
            for (int n = 0; n < 2; n++) {
                int c = n0 + n * 8 + 2 * tg;
                *(uint32_t*)&smh[base + OFF_V + r * VS + c] =
                    h2u(acc[m][n].x, acc[m][n].y);
                *(uint32_t*)&smh[base + OFF_V + (r + 8) * VS + c] =
                    h2u(acc[m][n].z, acc[m][n].w);
            }
        }
    }
    bar_named(1 + wh, 512);      // HB-B: Q, K, V visible within half

    // ---- scores + softmax + P@V, P fully register-resident ----
    const int h  = wrp >> 2;
    const int mt = wrp & 3;
    const int r0 = mt * 16 + g;
    {
        const uint32_t qA = smem_u32 +
            (uint32_t)(base + OFF_Q + (mt * 16 + aRow) * SH + h * 32 + aCol) * 2;
        uint32_t kB[3];
        #pragma unroll
        for (int nn = 0; nn < 3; nn++)
            kB[nn] = smem_u32 +
                (uint32_t)(base + OFF_K + (nn * 16 + bRow) * SH + h * 32 + bCol) * 2;
        const uint32_t kB2 = smem_u32 +
            (uint32_t)(base + OFF_K + (48 + (lane & 7)) * SH + h * 32 + bCol) * 2;

        float4 sacc[7];
        #pragma unroll
        for (int n = 0; n < 7; n++) sacc[n] = make_float4(0.f, 0.f, 0.f, 0.f);
        #pragma unroll
        for (int kt = 0; kt < 2; kt++) {
            uint32_t koff = kt * 32u;
            uint32_t Aq[4];
            ldsm_x4(Aq[0], Aq[1], Aq[2], Aq[3], qA + koff);
            #pragma unroll
            for (int nn = 0; nn < 3; nn++) {
                uint32_t Bk[4];
                ldsm_x4(Bk[0], Bk[1], Bk[2], Bk[3], kB[nn] + koff);
                mma16(sacc[2 * nn],     Aq[0], Aq[1], Aq[2], Aq[3], Bk[0], Bk[1]);
                mma16(sacc[2 * nn + 1], Aq[0], Aq[1], Aq[2], Aq[3], Bk[2], Bk[3]);
            }
            uint32_t b0, b1;
            ldsm_x2(b0, b1, kB2 + koff);
            mma16(sacc[6], Aq[0], Aq[1], Aq[2], Aq[3], b0, b1);
        }

        if (NTOK < 56) {
            #pragma unroll
            for (int n = 0; n < 7; n++) {
                int j0 = 8 * n + 2 * tg;
                if (j0 >= NTOK)     { sacc[n].x = -1e30f; sacc[n].z = -1e30f; }
                if (j0 + 1 >= NTOK) { sacc[n].y = -1e30f; sacc[n].w = -1e30f; }
            }
        }
        float mA = -1e30f, mB = -1e30f;
        #pragma unroll
        for (int n = 0; n < 7; n++) {
            mA = fmaxf(mA, fmaxf(sacc[n].x, sacc[n].y));
            mB = fmaxf(mB, fmaxf(sacc[n].z, sacc[n].w));
        }
        #pragma unroll
        for (int o = 1; o <= 2; o <<= 1) {
            mA = fmaxf(mA, __shfl_xor_sync(~0u, mA, o));
            mB = fmaxf(mB, __shfl_xor_sync(~0u, mB, o));
        }
        float sA = 0.f, sB = 0.f;
        #pragma unroll
        for (int n = 0; n < 7; n++) {
            sacc[n].x = __expf(sacc[n].x - mA);
            sacc[n].y = __expf(sacc[n].y - mA);
            sacc[n].z = __expf(sacc[n].z - mB);
            sacc[n].w = __expf(sacc[n].w - mB);
            sA += sacc[n].x + sacc[n].y;
            sB += sacc[n].z + sacc[n].w;
        }
        #pragma unroll
        for (int o = 1; o <= 2; o <<= 1) {
            sA += __shfl_xor_sync(~0u, sA, o);
            sB += __shfl_xor_sync(~0u, sB, o);
        }
        float iA = 1.0f / sA, iB = 1.0f / sB;

        uint32_t pA[7], pB[7];
        #pragma unroll
        for (int n = 0; n < 7; n++) {
            pA[n] = h2u(sacc[n].x * iA, sacc[n].y * iA);
            pB[n] = h2u(sacc[n].z * iB, sacc[n].w * iB);
        }

        // attn @ V: B-frags via ldmatrix.trans on plain-layout V
        const int li  = lane & 7;
        const int gq  = lane >> 3;
        float4 vacc[4];
        #pragma unroll
        for (int n = 0; n < 4; n++) vacc[n] = make_float4(0.f, 0.f, 0.f, 0.f);
        const uint32_t vB = smem_u32 + (uint32_t)
            (base + OFF_V + (((gq & 1) << 3) + li) * VS + h * 32 + ((gq >> 1) << 3)) * 2;
        #pragma unroll
        for (int kt = 0; kt < 4; kt++) {
            uint32_t addr = vB + (uint32_t)(kt * 16 * VS) * 2;
            uint32_t b00, b01, b10, b11;
            ldsm_x4_t(b00, b01, b10, b11, addr);
            uint32_t b20, b21, b30, b31;
            ldsm_x4_t(b20, b21, b30, b31, addr + 32);

            uint32_t a0 = pA[2 * kt], a1 = pB[2 * kt];
            uint32_t a2 = (2 * kt + 1 < 7) ? pA[2 * kt + 1] : 0u;  // j pad = 0
            uint32_t a3 = (2 * kt + 1 < 7) ? pB[2 * kt + 1] : 0u;
            mma16(vacc[0], a0, a1, a2, a3, b00, b01);
            mma16(vacc[1], a0, a1, a2, a3, b10, b11);
            mma16(vacc[2], a0, a1, a2, a3, b20, b21);
            mma16(vacc[3], a0, a1, a2, a3, b30, b31);
        }
        #pragma unroll
        for (int n = 0; n < 4; n++) {
            int c = h * 32 + n * 8 + 2 * tg;
            *(uint32_t*)&smh[base + OFF_X + r0 * SH + c]       = h2u(vacc[n].x, vacc[n].y);
            *(uint32_t*)&smh[base + OFF_X + (r0 + 8) * SH + c] = h2u(vacc[n].z, vacc[n].w);
        }
    }
    bar_named(1 + wh, 512);      // HB-C: attn output visible within half

    // ---- proj GEMM (W1 group rows) -> global ----
    {
        float4 acc[2][2];
        #pragma unroll
        for (int n = 0; n < 2; n++) {
            float b0 = projb[n0 + n * 8 + 2 * tg];
            float b1 = projb[n0 + n * 8 + 2 * tg + 1];
            acc[0][n] = make_float4(b0, b1, b0, b1);
            acc[1][n] = acc[0][n];
        }
        #pragma unroll 4
        for (int kt = 0; kt < 8; kt++) {
            uint32_t koff = kt * 32u;
            uint32_t A0[4], A1[4], Bv[4];
            ldsm_x4(A0[0], A0[1], A0[2], A0[3], xA0 + koff);
            ldsm_x4(A1[0], A1[1], A1[2], A1[3], xA1 + koff);
            ldsm_x4(Bv[0], Bv[1], Bv[2], Bv[3], wB1 + koff);
            mma16(acc[0][0], A0[0], A0[1], A0[2], A0[3], Bv[0], Bv[1]);
            mma16(acc[0][1], A0[0], A0[1], A0[2], A0[3], Bv[2], Bv[3]);
            mma16(acc[1][0], A1[0], A1[1], A1[2], A1[3], Bv[0], Bv[1]);
            mma16(acc[1][1], A1[0], A1[1], A1[2], A1[3], Bv[2], Bv[3]);
        }

        #pragma unroll
        for (int m = 0; m < 2; m++) {
            #pragma unroll
            for (int rr = 0; rr < 2; rr++) {
                int r = (mb + m) * 16 + g + rr * 8;
                if (r < NTOK) {
                    #pragma unroll
                    for (int n = 0; n < 2; n++) {
                        float2 val = rr ? make_float2(acc[m][n].z, acc[m][n].w)
                                        : make_float2(acc[m][n].x, acc[m][n].y);
                        size_t o = (size_t)tokidx[wh * 64 + r] * 128 + n0 + n * 8 + 2 * tg;
                        if (BRANCH == 0) {
                            *(float2*)&out[o] = val;
                        } else {
                            asm volatile("red.global.add.v2.f32 [%0], {%1, %2};"
                                         :: "l"(out + o), "f"(val.x), "f"(val.y)
                                         : "memory");
                        }
                    }
                }
            }
        }
    }
}

// xy alone (plain stores must precede the REDG accumulators)
__global__ void __launch_bounds__(1024, 1)
win_xy_k(const float* __restrict__ x, const float* __restrict__ qkvb,
         const float* __restrict__ projb, float* __restrict__ out) {
    win_body<0, 49>(blockIdx.x, x, qkvb, projb, out);
}

// th + tw merged: both accumulate via REDG (commutative) -> one tail
__global__ void __launch_bounds__(1024, 1)
win_thw_k(const float* __restrict__ x,
          const float* __restrict__ qkvb1, const float* __restrict__ projb1,
          const float* __restrict__ qkvb2, const float* __restrict__ projb2,
          float* __restrict__ out) {
    int b = blockIdx.x;
    if (b < 1792) win_body<1, 56>(b, x, qkvb1, projb1, out);
    else          win_body<2, 56>(b - 1792, x, qkvb2, projb2, out);
}

extern "C" void kernel_launch(void* const* d_in, const int* in_sizes, int n_in,
                              void* d_out, int out_size)
{
    const float* x         = (const float*)d_in[0];
    const float* qkv_w     = (const float*)d_in[1];
    const float* qkv_b     = (const float*)d_in[2];
    const float* qkv_th_w  = (const float*)d_in[3];
    const float* qkv_th_b  = (const float*)d_in[4];
    const float* qkv_tw_w  = (const float*)d_in[5];
    const float* qkv_tw_b  = (const float*)d_in[6];
    const float* proj_w    = (const float*)d_in[7];
    const float* proj_b    = (const float*)d_in[8];
    const float* proj_th_w = (const float*)d_in[9];
    const float* proj_th_b = (const float*)d_in[10];
    const float* proj_tw_w = (const float*)d_in[11];
    const float* proj_tw_b = (const float*)d_in[12];
    float* out = (float*)d_out;

    conv_weights<<<768, 256>>>(qkv_w, qkv_th_w, qkv_tw_w,
                               proj_w, proj_th_w, proj_tw_w);

    cudaFuncSetAttribute(win_xy_k,
                         cudaFuncAttributeMaxDynamicSharedMemorySize, SMEM_BYTES);
    cudaFuncSetAttribute(win_thw_k,
                         cudaFuncAttributeMaxDynamicSharedMemorySize, SMEM_BYTES);

    // xy writes every output exactly once; th+tw accumulate concurrently.
    win_xy_k<<<2048, 1024, SMEM_BYTES>>>(x, qkv_b, proj_b, out);
    win_thw_k<<<3584, 1024, SMEM_BYTES>>>(x, qkv_th_b, proj_th_b,
                                          qkv_tw_b, proj_tw_b, out);
}

// round 17
// speedup vs baseline: 1.4261x; 1.4261x over previous
#include <cuda_runtime.h>
#include <cuda_fp16.h>
#include <cstdint>

// Problem constants: B=8, D=8, H=W=56, C=128, 4 heads x 32, windows (8,7,7),
// all pads zero. xy: 4096 windows x 49 tok; th/tw: 3584 x 56.
//
// 2 windows per CTA (1024 thr). ldmatrix on plain row-major smem (stride 136
// halves -> conflict-free LDSM). P register-resident. q+k in one pass.
// R16 (= R14 + one reorder): v/proj restage is ISSUED at B2 and the wait is
// deferred until after scores+softmax (weight-independent work) -> staging
// latency fully hidden. P (pA/pB) stays live across the v chunk.
// CTA-wide cooperative staging (R15's per-group staging regressed: it
// serialized cp.async issue onto one warp). th/tw merged via REDG.

static constexpr int SH   = 136;  // stride (halves) X/Q/K rows
static constexpr int WSH  = 136;  // stride staged weight rows
static constexpr int VS   = 136;  // stride V rows

static constexpr int OFF_X  = 0;                    // 64 x SH (x, later attn out)
static constexpr int OFF_Q  = OFF_X + 64 * SH;
static constexpr int OFF_K  = OFF_Q + 64 * SH;
static constexpr int OFF_V  = OFF_K + 64 * SH;
static constexpr int ACT_HALVES = OFF_V + 64 * VS;  // 34816
static constexpr int OFF_W0 = 2 * ACT_HALVES;       // weight buffer 0
static constexpr int OFF_W1 = OFF_W0 + 128 * WSH;   // weight buffer 1
static constexpr int TOT_HALVES = OFF_W1 + 128 * WSH;          // 104448
static constexpr int SMEM_BYTES = TOT_HALVES * 2 + 128 * 4;    // 209408 (1 CTA/SM)

// Pre-converted fp16 weights, PLAIN transposed: [n][k].
__device__ __align__(16) __half g_qkvwt[3][384 * 128];
__device__ __align__(16) __half g_projwt[3][128 * 128];

template <int BRANCH>
__device__ __forceinline__ int tok_index(int win, int tt) {
    if (BRANCH == 0) {                 // xy: (b, d, hb, wb) x (hh, ww)
        int b  = win >> 9;
        int d  = (win >> 6) & 7;
        int hb = (win >> 3) & 7;
        int wb = win & 7;
        int hh = tt / 7, wq = tt - hh * 7;
        return ((b * 8 + d) * 56 + hb * 7 + hh) * 56 + wb * 7 + wq;
    } else if (BRANCH == 1) {          // th: (b, hb, w) x (dd, hh)
        int b  = win / 448;
        int r  = win - b * 448;
        int hb = r / 56;
        int w  = r - hb * 56;
        int dd = tt / 7, hh = tt - dd * 7;
        return ((b * 8 + dd) * 56 + hb * 7 + hh) * 56 + w;
    } else {                           // tw: (b, h, wb) x (dd, ww)
        int b  = win / 448;
        int r  = win - b * 448;
        int h  = r >> 3;
        int wb = r & 7;
        int dd = tt / 7, wq = tt - dd * 7;
        return ((b * 8 + dd) * 56 + h) * 56 + wb * 7 + wq;
    }
}

__device__ __forceinline__ void mma16(float4& d, uint32_t a0, uint32_t a1,
                                      uint32_t a2, uint32_t a3,
                                      uint32_t b0, uint32_t b1) {
    asm volatile(
        "mma.sync.aligned.m16n8k16.row.col.f32.f16.f16.f32 "
        "{%0,%1,%2,%3}, {%4,%5,%6,%7}, {%8,%9}, {%0,%1,%2,%3};\n"
        : "+f"(d.x), "+f"(d.y), "+f"(d.z), "+f"(d.w)
        : "r"(a0), "r"(a1), "r"(a2), "r"(a3), "r"(b0), "r"(b1));
}

__device__ __forceinline__ void ldsm_x4(uint32_t& r0, uint32_t& r1,
                                        uint32_t& r2, uint32_t& r3, uint32_t addr) {
    asm volatile("ldmatrix.sync.aligned.m8n8.x4.shared.b16 {%0,%1,%2,%3}, [%4];"
                 : "=r"(r0), "=r"(r1), "=r"(r2), "=r"(r3) : "r"(addr));
}
__device__ __forceinline__ void ldsm_x2(uint32_t& r0, uint32_t& r1, uint32_t addr) {
    asm volatile("ldmatrix.sync.aligned.m8n8.x2.shared.b16 {%0,%1}, [%2];"
                 : "=r"(r0), "=r"(r1) : "r"(addr));
}
__device__ __forceinline__ void ldsm_x4_t(uint32_t& r0, uint32_t& r1,
                                          uint32_t& r2, uint32_t& r3, uint32_t addr) {
    asm volatile("ldmatrix.sync.aligned.m8n8.x4.trans.shared.b16 {%0,%1,%2,%3}, [%4];"
                 : "=r"(r0), "=r"(r1), "=r"(r2), "=r"(r3) : "r"(addr));
}

__device__ __forceinline__ void cp16(uint32_t dst, const void* src) {
    asm volatile("cp.async.cg.shared.global [%0], [%1], 16;" :: "r"(dst), "l"(src));
}
__device__ __forceinline__ void cp_commit() {
    asm volatile("cp.async.commit_group;" ::: "memory");
}
template <int N>
__device__ __forceinline__ void cp_wait() {
    asm volatile("cp.async.wait_group %0;" :: "n"(N) : "memory");
}
__device__ __forceinline__ void bar_half(int id) {
    asm volatile("bar.sync %0, 512;" :: "r"(id) : "memory");
}

__device__ __forceinline__ uint32_t h2u(float a, float b) {
    __half2 h = __floats2half2_rn(a, b);
    return *(uint32_t*)&h;
}

// ---------------- weight pre-conversion (plain transpose) ----------------
__global__ void conv_weights(const float* __restrict__ w0, const float* __restrict__ w1,
                             const float* __restrict__ w2, const float* __restrict__ p0,
                             const float* __restrict__ p1, const float* __restrict__ p2) {
    int tid = blockIdx.x * 256 + threadIdx.x;
    const int QK = 3 * 384 * 128;
    if (tid < QK) {
        int br  = tid / (384 * 128);
        int rem = tid - br * 384 * 128;
        int n = rem >> 7, k = rem & 127;
        const float* src = (br == 0) ? w0 : (br == 1 ? w1 : w2);
        g_qkvwt[br][rem] = __float2half_rn(src[k * 384 + n]);
    } else {
        int t2  = tid - QK;
        int br  = t2 / (128 * 128);
        int rem = t2 - br * 16384;
        int n = rem >> 7, k = rem & 127;
        const float* src = (br == 0) ? p0 : (br == 1 ? p1 : p2);
        g_projwt[br][rem] = __float2half_rn(src[k * 128 + n]);
    }
}

// ------------- fused window attention body, TWO windows per CTA -------------
template <int BRANCH, int NTOK>
__device__ __forceinline__ void
win_body(int cta, const float* __restrict__ x,
         const float* __restrict__ qkvb, const float* __restrict__ projb,
         float* __restrict__ out)
{
    extern __shared__ __align__(16) __half smh[];
    int* tokidx = (int*)(smh + TOT_HALVES);
    const uint32_t smem_u32 = (uint32_t)__cvta_generic_to_shared(smh);

    const int t    = threadIdx.x;          // 0..1023
    const int wh   = t >> 9;               // window half 0/1
    const int tl   = t & 511;
    const int lane = t & 31;
    const int wrp  = tl >> 5;              // local warp 0..15
    const int g    = lane >> 2;
    const int tg   = lane & 3;
    const int win  = cta * 2 + wh;
    const int base = wh * ACT_HALVES;

    const int aRow = lane & 15;
    const int aCol = (lane >> 4) << 3;
    const int bRow = (lane & 7) + ((lane >> 4) << 3);
    const int bCol = ((lane >> 3) & 1) << 3;

    // ---- stage q->W0, k->W1 BEFORE x-load (CTA-wide cooperative) ----
    {
        const __half* wq = g_qkvwt[BRANCH];
        const __half* wk = g_qkvwt[BRANCH] + 128 * 128;
        for (int idx = t; idx < 128 * 16; idx += 1024) {
            int rw = idx >> 4, c8 = idx & 15;
            cp16(smem_u32 + (uint32_t)(OFF_W0 + rw * WSH + c8 * 8) * 2,
                 wq + rw * 128 + c8 * 8);
            cp16(smem_u32 + (uint32_t)(OFF_W1 + rw * WSH + c8 * 8) * 2,
                 wk + rw * 128 + c8 * 8);
        }
        cp_commit();
    }

    if (tl < NTOK) tokidx[wh * 64 + tl] = tok_index<BRANCH>(win, tl);

    // ---- x -> X (fp16, plain rows), pad rows zeroed ----
    for (int idx = tl; idx < 64 * 32; idx += 512) {
        int r = idx >> 5, q = idx & 31;
        uint2 u = make_uint2(0u, 0u);
        if (r < NTOK) {
            float4 v = *(const float4*)
                (x + (size_t)tok_index<BRANCH>(win, r) * 128 + q * 4);
            u.x = h2u(v.x, v.y);
            u.y = h2u(v.z, v.w);
        }
        *(uint2*)&smh[base + OFF_X + r * SH + q * 4] = u;
    }

    const int mb = (wrp & 1) * 2;        // m-tiles {mb, mb+1}
    const int n0 = (wrp >> 1) * 16;      // n columns [n0, n0+16)
    const float qscale = 0.1767766952966369f;

    const uint32_t xA0 = smem_u32 +
        (uint32_t)(base + OFF_X + (mb * 16 + aRow) * SH + aCol) * 2;
    const uint32_t xA1 = xA0 + 16u * SH * 2u;
    const uint32_t wB0 = smem_u32 + (uint32_t)(OFF_W0 + (n0 + bRow) * WSH + bCol) * 2;
    const uint32_t wB1 = smem_u32 + (uint32_t)(OFF_W1 + (n0 + bRow) * WSH + bCol) * 2;

    // ---- q + k in ONE pass (A loaded once, B from W0 and W1) ----
    cp_wait<0>();
    __syncthreads();     // B1: x + q/k weights visible
    {
        float4 accq[2][2], acck[2][2];
        #pragma unroll
        for (int n = 0; n < 2; n++) {
            float q0 = qkvb[n0 + n * 8 + 2 * tg];
            float q1 = qkvb[n0 + n * 8 + 2 * tg + 1];
            float k0 = qkvb[128 + n0 + n * 8 + 2 * tg];
            float k1 = qkvb[128 + n0 + n * 8 + 2 * tg + 1];
            accq[0][n] = make_float4(q0, q1, q0, q1);
            accq[1][n] = accq[0][n];
            acck[0][n] = make_float4(k0, k1, k0, k1);
            acck[1][n] = acck[0][n];
        }
        #pragma unroll 2
        for (int kt = 0; kt < 8; kt++) {
            uint32_t koff = kt * 32u;
            uint32_t A0[4], A1[4], Bq[4], Bk[4];
            ldsm_x4(A0[0], A0[1], A0[2], A0[3], xA0 + koff);
            ldsm_x4(A1[0], A1[1], A1[2], A1[3], xA1 + koff);
            ldsm_x4(Bq[0], Bq[1], Bq[2], Bq[3], wB0 + koff);
            ldsm_x4(Bk[0], Bk[1], Bk[2], Bk[3], wB1 + koff);
            mma16(accq[0][0], A0[0], A0[1], A0[2], A0[3], Bq[0], Bq[1]);
            mma16(accq[0][1], A0[0], A0[1], A0[2], A0[3], Bq[2], Bq[3]);
            mma16(accq[1][0], A1[0], A1[1], A1[2], A1[3], Bq[0], Bq[1]);
            mma16(accq[1][1], A1[0], A1[1], A1[2], A1[3], Bq[2], Bq[3]);
            mma16(acck[0][0], A0[0], A0[1], A0[2], A0[3], Bk[0], Bk[1]);
            mma16(acck[0][1], A0[0], A0[1], A0[2], A0[3], Bk[2], Bk[3]);
            mma16(acck[1][0], A1[0], A1[1], A1[2], A1[3], Bk[0], Bk[1]);
            mma16(acck[1][1], A1[0], A1[1], A1[2], A1[3], Bk[2], Bk[3]);
        }
        #pragma unroll
        for (int m = 0; m < 2; m++) {
            int r = (mb + m) * 16 + g;
            #pragma unroll
            for (int n = 0; n < 2; n++) {
                int c = n0 + n * 8 + 2 * tg;
                *(uint32_t*)&smh[base + OFF_Q + r * SH + c] =
                    h2u(accq[m][n].x * qscale, accq[m][n].y * qscale);
                *(uint32_t*)&smh[base + OFF_Q + (r + 8) * SH + c] =
                    h2u(accq[m][n].z * qscale, accq[m][n].w * qscale);
                *(uint32_t*)&smh[base + OFF_K + r * SH + c] =
                    h2u(acck[m][n].x, acck[m][n].y);
                *(uint32_t*)&smh[base + OFF_K + (r + 8) * SH + c] =
                    h2u(acck[m][n].z, acck[m][n].w);
            }
        }
    }
    __syncthreads();     // B2: Q/K visible; W0+W1 free for restage

    // ---- ISSUE restage v->W0, proj->W1 (wait deferred past scores) ----
    {
        const __half* wv = g_qkvwt[BRANCH] + 2 * 128 * 128;
        const __half* pw = g_projwt[BRANCH];
        for (int idx = t; idx < 128 * 16; idx += 1024) {
            int rw = idx >> 4, c8 = idx & 15;
            cp16(smem_u32 + (uint32_t)(OFF_W0 + rw * WSH + c8 * 8) * 2,
                 wv + rw * 128 + c8 * 8);
            cp16(smem_u32 + (uint32_t)(OFF_W1 + rw * WSH + c8 * 8) * 2,
                 pw + rw * 128 + c8 * 8);
        }
        cp_commit();
    }

    // ---- scores + softmax (hides staging); P packed into registers ----
    const int h  = wrp >> 2;
    const int mt = wrp & 3;
    const int r0 = mt * 16 + g;
    uint32_t pA[7], pB[7];
    {
        const uint32_t qA = smem_u32 +
            (uint32_t)(base + OFF_Q + (mt * 16 + aRow) * SH + h * 32 + aCol) * 2;
        uint32_t kB[3];
        #pragma unroll
        for (int nn = 0; nn < 3; nn++)
            kB[nn] = smem_u32 +
                (uint32_t)(base + OFF_K + (nn * 16 + bRow) * SH + h * 32 + bCol) * 2;
        const uint32_t kB2 = smem_u32 +
            (uint32_t)(base + OFF_K + (48 + (lane & 7)) * SH + h * 32 + bCol) * 2;

        float4 sacc[7];
        #pragma unroll
        for (int n = 0; n < 7; n++) sacc[n] = make_float4(0.f, 0.f, 0.f, 0.f);
        #pragma unroll
        for (int kt = 0; kt < 2; kt++) {
            uint32_t koff = kt * 32u;
            uint32_t Aq[4];
            ldsm_x4(Aq[0], Aq[1], Aq[2], Aq[3], qA + koff);
            #pragma unroll
            for (int nn = 0; nn < 3; nn++) {
                uint32_t Bk[4];
                ldsm_x4(Bk[0], Bk[1], Bk[2], Bk[3], kB[nn] + koff);
                mma16(sacc[2 * nn],     Aq[0], Aq[1], Aq[2], Aq[3], Bk[0], Bk[1]);
                mma16(sacc[2 * nn + 1], Aq[0], Aq[1], Aq[2], Aq[3], Bk[2], Bk[3]);
            }
            uint32_t b0, b1;
            ldsm_x2(b0, b1, kB2 + koff);
            mma16(sacc[6], Aq[0], Aq[1], Aq[2], Aq[3], b0, b1);
        }

        if (NTOK < 56) {
            #pragma unroll
            for (int n = 0; n < 7; n++) {
                int j0 = 8 * n + 2 * tg;
                if (j0 >= NTOK)     { sacc[n].x = -1e30f; sacc[n].z = -1e30f; }
                if (j0 + 1 >= NTOK) { sacc[n].y = -1e30f; sacc[n].w = -1e30f; }
            }
        }
        float mA = -1e30f, mB = -1e30f;
        #pragma unroll
        for (int n = 0; n < 7; n++) {
            mA = fmaxf(mA, fmaxf(sacc[n].x, sacc[n].y));
            mB = fmaxf(mB, fmaxf(sacc[n].z, sacc[n].w));
        }
        #pragma unroll
        for (int o = 1; o <= 2; o <<= 1) {
            mA = fmaxf(mA, __shfl_xor_sync(~0u, mA, o));
            mB = fmaxf(mB, __shfl_xor_sync(~0u, mB, o));
        }
        float sA = 0.f, sB = 0.f;
        #pragma unroll
        for (int n = 0; n < 7; n++) {
            sacc[n].x = __expf(sacc[n].x - mA);
            sacc[n].y = __expf(sacc[n].y - mA);
            sacc[n].z = __expf(sacc[n].z - mB);
            sacc[n].w = __expf(sacc[n].w - mB);
            sA += sacc[n].x + sacc[n].y;
            sB += sacc[n].z + sacc[n].w;
        }
        #pragma unroll
        for (int o = 1; o <= 2; o <<= 1) {
            sA += __shfl_xor_sync(~0u, sA, o);
            sB += __shfl_xor_sync(~0u, sB, o);
        }
        float iA = 1.0f / sA, iB = 1.0f / sB;
        #pragma unroll
        for (int n = 0; n < 7; n++) {
            pA[n] = h2u(sacc[n].x * iA, sacc[n].y * iA);
            pB[n] = h2u(sacc[n].z * iB, sacc[n].w * iB);
        }
    }

    // ---- now consume the restaged weights ----
    cp_wait<0>();
    __syncthreads();     // B3: v + proj weights visible

    // ---- v chunk (W0) ----
    {
        float4 acc[2][2];
        #pragma unroll
        for (int n = 0; n < 2; n++) {
            float b0 = qkvb[256 + n0 + n * 8 + 2 * tg];
            float b1 = qkvb[256 + n0 + n * 8 + 2 * tg + 1];
            acc[0][n] = make_float4(b0, b1, b0, b1);
            acc[1][n] = acc[0][n];
        }
        #pragma unroll 4
        for (int kt = 0; kt < 8; kt++) {
            uint32_t koff = kt * 32u;
            uint32_t A0[4], A1[4], Bv[4];
            ldsm_x4(A0[0], A0[1], A0[2], A0[3], xA0 + koff);
            ldsm_x4(A1[0], A1[1], A1[2], A1[3], xA1 + koff);
            ldsm_x4(Bv[0], Bv[1], Bv[2], Bv[3], wB0 + koff);
            mma16(acc[0][0], A0[0], A0[1], A0[2], A0[3], Bv[0], Bv[1]);
            mma16(acc[0][1], A0[0], A0[1], A0[2], A0[3], Bv[2], Bv[3]);
            mma16(acc[1][0], A1[0], A1[1], A1[2], A1[3], Bv[0], Bv[1]);
            mma16(acc[1][1], A1[0], A1[1], A1[2], A1[3], Bv[2], Bv[3]);
        }
        #pragma unroll
        for (int m = 0; m < 2; m++) {
            int r = (mb + m) * 16 + g;
            #pragma unroll
            for (int n = 0; n < 2; n++) {
                int c = n0 + n * 8 + 2 * tg;
                *(uint32_t*)&smh[base + OFF_V + r * VS + c] =
                    h2u(acc[m][n].x, acc[m][n].y);
                *(uint32_t*)&smh[base + OFF_V + (r + 8) * VS + c] =
                    h2u(acc[m][n].z, acc[m][n].w);
            }
        }
    }
    bar_half(1 + wh);    // HB-B: V visible within half

    // ---- attn @ V (register P), write attnout into X region ----
    {
        const int li  = lane & 7;
        const int gq  = lane >> 3;
        float4 vacc[4];
        #pragma unroll
        for (int n = 0; n < 4; n++) vacc[n] = make_float4(0.f, 0.f, 0.f, 0.f);
        const uint32_t vB = smem_u32 + (uint32_t)
            (base + OFF_V + (((gq & 1) << 3) + li) * VS + h * 32 + ((gq >> 1) << 3)) * 2;
        #pragma unroll
        for (int kt = 0; kt < 4; kt++) {
            uint32_t addr = vB + (uint32_t)(kt * 16 * VS) * 2;
            uint32_t b00, b01, b10, b11;
            ldsm_x4_t(b00, b01, b10, b11, addr);
            uint32_t b20, b21, b30, b31;
            ldsm_x4_t(b20, b21, b30, b31, addr + 32);

            uint32_t a0 = pA[2 * kt], a1 = pB[2 * kt];
            uint32_t a2 = (2 * kt + 1 < 7) ? pA[2 * kt + 1] : 0u;  // j pad = 0
            uint32_t a3 = (2 * kt + 1 < 7) ? pB[2 * kt + 1] : 0u;
            mma16(vacc[0], a0, a1, a2, a3, b00, b01);
            mma16(vacc[1], a0, a1, a2, a3, b10, b11);
            mma16(vacc[2], a0, a1, a2, a3, b20, b21);
            mma16(vacc[3], a0, a1, a2, a3, b30, b31);
        }
        #pragma unroll
        for (int n = 0; n < 4; n++) {
            int c = h * 32 + n * 8 + 2 * tg;
            *(uint32_t*)&smh[base + OFF_X + r0 * SH + c]       = h2u(vacc[n].x, vacc[n].y);
            *(uint32_t*)&smh[base + OFF_X + (r0 + 8) * SH + c] = h2u(vacc[n].z, vacc[n].w);
        }
    }
    bar_half(1 + wh);    // HB-C: attn output visible within half

    // ---- proj GEMM (W1) -> global ----
    {
        float4 acc[2][2];
        #pragma unroll
        for (int n = 0; n < 2; n++) {
            float b0 = projb[n0 + n * 8 + 2 * tg];
            float b1 = projb[n0 + n * 8 + 2 * tg + 1];
            acc[0][n] = make_float4(b0, b1, b0, b1);
            acc[1][n] = acc[0][n];
        }
        #pragma unroll 4
        for (int kt = 0; kt < 8; kt++) {
            uint32_t koff = kt * 32u;
            uint32_t A0[4], A1[4], Bv[4];
            ldsm_x4(A0[0], A0[1], A0[2], A0[3], xA0 + koff);
            ldsm_x4(A1[0], A1[1], A1[2], A1[3], xA1 + koff);
            ldsm_x4(Bv[0], Bv[1], Bv[2], Bv[3], wB1 + koff);
            mma16(acc[0][0], A0[0], A0[1], A0[2], A0[3], Bv[0], Bv[1]);
            mma16(acc[0][1], A0[0], A0[1], A0[2], A0[3], Bv[2], Bv[3]);
            mma16(acc[1][0], A1[0], A1[1], A1[2], A1[3], Bv[0], Bv[1]);
            mma16(acc[1][1], A1[0], A1[1], A1[2], A1[3], Bv[2], Bv[3]);
        }

        #pragma unroll
        for (int m = 0; m < 2; m++) {
            #pragma unroll
            for (int rr = 0; rr < 2; rr++) {
                int r = (mb + m) * 16 + g + rr * 8;
                if (r < NTOK) {
                    #pragma unroll
                    for (int n = 0; n < 2; n++) {
                        float2 val = rr ? make_float2(acc[m][n].z, acc[m][n].w)
                                        : make_float2(acc[m][n].x, acc[m][n].y);
                        size_t o = (size_t)tokidx[wh * 64 + r] * 128 + n0 + n * 8 + 2 * tg;
                        if (BRANCH == 0) {
                            *(float2*)&out[o] = val;
                        } else {
                            asm volatile("red.global.add.v2.f32 [%0], {%1, %2};"
                                         :: "l"(out + o), "f"(val.x), "f"(val.y)
                                         : "memory");
                        }
                    }
                }
            }
        }
    }
}

// xy alone (plain stores must precede the REDG accumulators)
__global__ void __launch_bounds__(1024, 1)
win_xy_k(const float* __restrict__ x, const float* __restrict__ qkvb,
         const float* __restrict__ projb, float* __restrict__ out) {
    win_body<0, 49>(blockIdx.x, x, qkvb, projb, out);
}

// th + tw merged: both accumulate via REDG (commutative) -> one tail
__global__ void __launch_bounds__(1024, 1)
win_thw_k(const float* __restrict__ x,
          const float* __restrict__ qkvb1, const float* __restrict__ projb1,
          const float* __restrict__ qkvb2, const float* __restrict__ projb2,
          float* __restrict__ out) {
    int b = blockIdx.x;
    if (b < 1792) win_body<1, 56>(b, x, qkvb1, projb1, out);
    else          win_body<2, 56>(b - 1792, x, qkvb2, projb2, out);
}

extern "C" void kernel_launch(void* const* d_in, const int* in_sizes, int n_in,
                              void* d_out, int out_size)
{
    const float* x         = (const float*)d_in[0];
    const float* qkv_w     = (const float*)d_in[1];
    const float* qkv_b     = (const float*)d_in[2];
    const float* qkv_th_w  = (const float*)d_in[3];
    const float* qkv_th_b  = (const float*)d_in[4];
    const float* qkv_tw_w  = (const float*)d_in[5];
    const float* qkv_tw_b  = (const float*)d_in[6];
    const float* proj_w    = (const float*)d_in[7];
    const float* proj_b    = (const float*)d_in[8];
    const float* proj_th_w = (const float*)d_in[9];
    const float* proj_th_b = (const float*)d_in[10];
    const float* proj_tw_w = (const float*)d_in[11];
    const float* proj_tw_b = (const float*)d_in[12];
    float* out = (float*)d_out;

    conv_weights<<<768, 256>>>(qkv_w, qkv_th_w, qkv_tw_w,
                               proj_w, proj_th_w, proj_tw_w);

    cudaFuncSetAttribute(win_xy_k,
                         cudaFuncAttributeMaxDynamicSharedMemorySize, SMEM_BYTES);
    cudaFuncSetAttribute(win_thw_k,
                         cudaFuncAttributeMaxDynamicSharedMemorySize, SMEM_BYTES);

    // xy writes every output exactly once; th+tw accumulate concurrently.
    win_xy_k<<<2048, 1024, SMEM_BYTES>>>(x, qkv_b, proj_b, out);
    win_thw_k<<<3584, 1024, SMEM_BYTES>>>(x, qkv_th_b, proj_th_b,
                                          qkv_tw_b, proj_tw_b, out);
}